// round 8
// baseline (speedup 1.0000x reference)
#include <cuda_runtime.h>
#include <cuda_fp16.h>
#include <cstdint>
#include <math.h>

// ---------------- problem dims ----------------
#define T_TOK 8192
#define DIM   1024
#define NEXP  8
#define H1DIM 4096
#define H2DIM 2048
#define TPAD  9216
#define MAX_TILES 72

// ---------------- GEMM tile config ----------------
#define BM 128
#define BN 128
#define BK 32
#define NASTAGE 3                            // A f16 ring
#define APITCH 40                            // halfs/row; 20 words -> 8 rows distinct banks
#define BPITCH 136                           // halfs/row f16 B; proven conflict-free
// smem layout (bytes, per CTA):
#define A_TILE_B   (BM * APITCH * 2)         // 10240
#define BF16_TILE_B (BK * BPITCH * 2)        // 8704
#define BF32_TILE_B (BK * 128 * 4)           // 16384
#define OFF_A      0
#define OFF_BF16   (NASTAGE * A_TILE_B)                  // 30720
#define OFF_BF32   (OFF_BF16 + 2 * BF16_TILE_B)          // 48128
#define SMEM_BYTES (OFF_BF32 + 2 * BF32_TILE_B)          // 80896 -> 2 CTAs/SM

// ---------------- device scratch ----------------
__device__ int g_expert_id[T_TOK];
__device__ int g_counts[NEXP];
__device__ int g_cursor[NEXP];
__device__ int g_offsets[NEXP];
__device__ int g_tok[TPAD];
__device__ int g_tile_expert[MAX_TILES];
__device__ int g_tile_row[MAX_TILES];
__device__ __half g_xg[(size_t)TPAD * DIM];
__device__ __half g_h1[(size_t)TPAD * H1DIM];
__device__ __half g_h2[(size_t)TPAD * H2DIM];

// ---------------- helpers ----------------
__device__ __forceinline__ void mma16(float* c, const uint32_t* a, const uint32_t* b) {
    asm volatile(
        "mma.sync.aligned.m16n8k16.row.col.f32.f16.f16.f32 "
        "{%0,%1,%2,%3}, {%4,%5,%6,%7}, {%8,%9}, {%0,%1,%2,%3};\n"
        : "+f"(c[0]), "+f"(c[1]), "+f"(c[2]), "+f"(c[3])
        : "r"(a[0]), "r"(a[1]), "r"(a[2]), "r"(a[3]), "r"(b[0]), "r"(b[1]));
}

__device__ __forceinline__ void ldm4(uint32_t* r, uint32_t addr) {
    asm volatile("ldmatrix.sync.aligned.m8n8.x4.shared.b16 {%0,%1,%2,%3}, [%4];"
                 : "=r"(r[0]), "=r"(r[1]), "=r"(r[2]), "=r"(r[3]) : "r"(addr));
}
__device__ __forceinline__ void ldm4t(uint32_t* r, uint32_t addr) {
    asm volatile("ldmatrix.sync.aligned.m8n8.x4.trans.shared.b16 {%0,%1,%2,%3}, [%4];"
                 : "=r"(r[0]), "=r"(r[1]), "=r"(r[2]), "=r"(r[3]) : "r"(addr));
}

__device__ __forceinline__ void cpa16(uint32_t smem_addr, const void* gptr) {
    asm volatile("cp.async.cg.shared.global [%0], [%1], 16;\n"
                 :: "r"(smem_addr), "l"(gptr));
}
__device__ __forceinline__ void cp_commit() { asm volatile("cp.async.commit_group;\n"); }
template <int N>
__device__ __forceinline__ void cp_wait() { asm volatile("cp.async.wait_group %0;\n" :: "n"(N)); }

__device__ __forceinline__ float gelu_exact(float v) {
    return 0.5f * v * (1.0f + erff(v * 0.70710678118654752f));
}

// ---------------- routing phases ----------------
__global__ void init_kernel() {
    size_t i = (size_t)blockIdx.x * 256 + threadIdx.x;
    if (i < TPAD) g_tok[i] = -1;
    if (i < NEXP) { g_counts[i] = 0; g_cursor[i] = 0; }
    size_t n16 = (size_t)TPAD * DIM / 8;
    for (size_t j = i; j < n16; j += (size_t)gridDim.x * 256)
        ((uint4*)g_xg)[j] = make_uint4(0, 0, 0, 0);
}

__global__ void router_kernel(const float* __restrict__ x,
                              const float* __restrict__ Wr,
                              const float* __restrict__ br) {
    __shared__ float s_wr[DIM * NEXP];
    __shared__ float s_br[NEXP];
    int tid = threadIdx.x;
    for (int i = tid; i < DIM * NEXP / 4; i += 256)
        ((float4*)s_wr)[i] = ((const float4*)Wr)[i];
    if (tid < NEXP) s_br[tid] = br[tid];
    __syncthreads();

    int warp = tid >> 5, lane = tid & 31;
    int t = blockIdx.x * 8 + warp;

    float acc[NEXP];
#pragma unroll
    for (int e = 0; e < NEXP; e++) acc[e] = 0.0f;
    const float* xr = x + (size_t)t * DIM;
    for (int d = lane; d < DIM; d += 32) {
        float xv = xr[d];
#pragma unroll
        for (int e = 0; e < NEXP; e++) acc[e] += xv * s_wr[d * NEXP + e];
    }
#pragma unroll
    for (int e = 0; e < NEXP; e++)
        for (int o = 16; o; o >>= 1) acc[e] += __shfl_down_sync(0xffffffffu, acc[e], o);

    if (lane == 0) {
        float best = acc[0] + s_br[0];
        int bi = 0;
        for (int e = 1; e < NEXP; e++) {
            float v = acc[e] + s_br[e];
            if (v > best) { best = v; bi = e; }   // first-max == jnp.argmax
        }
        g_expert_id[t] = bi;
        atomicAdd(&g_counts[bi], 1);
    }
}

__global__ void schedule_kernel() {
    if (threadIdx.x == 0 && blockIdx.x == 0) {
        int off = 0, t = 0;
        for (int e = 0; e < NEXP; e++) {
            g_offsets[e] = off;
            int c = g_counts[e];
            int tiles = (c + BM - 1) >> 7;
            for (int i = 0; i < tiles; i++) {
                g_tile_expert[t] = e;
                g_tile_row[t] = off + i * BM;
                t++;
            }
            off += tiles << 7;
        }
        for (; t < MAX_TILES; t++) { g_tile_expert[t] = -1; g_tile_row[t] = 0; }
    }
}

// fused scatter + gather + f16 convert: one block per token
__global__ void scatter_gather_kernel(const float* __restrict__ x) {
    __shared__ int s_pos;
    int t = blockIdx.x;
    if (threadIdx.x == 0) {
        int e = g_expert_id[t];
        int pos = g_offsets[e] + atomicAdd(&g_cursor[e], 1);
        g_tok[pos] = t;
        s_pos = pos;
    }
    __syncthreads();
    int pos = s_pos;
    const float4* xr = (const float4*)(x + (size_t)t * DIM);
    uint2* orow = (uint2*)(g_xg + (size_t)pos * DIM);
#pragma unroll
    for (int i = 0; i < 2; i++) {
        int c = threadIdx.x + i * 128;
        float4 v = xr[c];
        __half2 h0 = __floats2half2_rn(v.x, v.y);
        __half2 h1 = __floats2half2_rn(v.z, v.w);
        orow[c] = make_uint2(*(uint32_t*)&h0, *(uint32_t*)&h1);
    }
}

// ---------------- grouped GEMM: fp16 mma, in-smem f32->f16 weight convert ---
// A [rows][K] fp16 grouped/padded (K-major).  B = W [E][K][N] fp32 (original
// layout). B staged f32 via cp.async, converted to f16 in smem one stage ahead,
// consumed via ldmatrix.x4.trans.  Block 128x128, warp 64x32, BK=32.
template <bool DO_GELU, bool SCATTER>
__global__ void __launch_bounds__(256, 2)
moe_gemm(const __half* __restrict__ A, const float* __restrict__ W,
         const float* __restrict__ bias, void* __restrict__ OutV,
         int K, int N, int ldo) {
    int e = g_tile_expert[blockIdx.y];
    if (e < 0) return;
    int row0 = g_tile_row[blockIdx.y];
    int n0 = blockIdx.x * BN;

    extern __shared__ char smem[];
    int tid = threadIdx.x;
    int wid = tid >> 5, lane = tid & 31;

    const __half* Ap = A + (size_t)row0 * K;
    const float* Bp = W + (size_t)e * K * N + n0;    // row k stride = N (f32)

    uint32_t smem_u = (uint32_t)__cvta_generic_to_shared(smem);
    uint32_t aBase = smem_u + OFF_A;
    uint32_t bf16Base = smem_u + OFF_BF16;
    uint32_t bf32Base = smem_u + OFF_BF32;

    // per stage: A 512 chunks(16B) + B f32 1024 chunks = 1536 -> 6/thread
    auto load_stage = [&](int j) {
        uint32_t aT = aBase + (uint32_t)(j % NASTAGE) * A_TILE_B;
        uint32_t sT = bf32Base + (uint32_t)(j & 1) * BF32_TILE_B;
        int kk = j * BK;
#pragma unroll
        for (int i = 0; i < 6; i++) {
            int c = tid + i * 256;
            if (c < 512) {                       // A: 128 rows x 4 chunks of 8 halfs
                int r = c >> 2, c4 = c & 3;
                cpa16(aT + (uint32_t)(r * APITCH + c4 * 8) * 2,
                      Ap + (size_t)r * K + kk + c4 * 8);
            } else {                             // B f32: 32 rows x 32 chunks of 4 f32
                int cb = c - 512;
                int r = cb >> 5, c4 = cb & 31;
                cpa16(sT + (uint32_t)(r * 128 + c4 * 4) * 4,
                      Bp + (size_t)(kk + r) * N + c4 * 4);
            }
        }
    };

    // convert stage j: staging[j&1] f32 -> f16 tile[j&1]; 16 f32 per thread
    auto convert_stage = [&](int j) {
        const float* sT = (const float*)(smem + OFF_BF32 + (j & 1) * BF32_TILE_B);
        __half* dT = (__half*)(smem + OFF_BF16 + (j & 1) * BF16_TILE_B);
#pragma unroll
        for (int i = 0; i < 2; i++) {
            int c = tid + i * 256;               // 512 out-chunks of 8 halfs
            int r = c >> 4, c8 = c & 15;
            const float4* src = (const float4*)(sT + r * 128 + c8 * 8);
            float4 a = src[0], b = src[1];
            __half2 h0 = __floats2half2_rn(a.x, a.y);
            __half2 h1 = __floats2half2_rn(a.z, a.w);
            __half2 h2 = __floats2half2_rn(b.x, b.y);
            __half2 h3 = __floats2half2_rn(b.z, b.w);
            uint4 o;
            o.x = *(uint32_t*)&h0; o.y = *(uint32_t*)&h1;
            o.z = *(uint32_t*)&h2; o.w = *(uint32_t*)&h3;
            *(uint4*)(dT + r * BPITCH + c8 * 8) = o;
        }
    };

    float acc[4][4][4];
#pragma unroll
    for (int mf = 0; mf < 4; mf++)
#pragma unroll
        for (int nf = 0; nf < 4; nf++)
#pragma unroll
            for (int i = 0; i < 4; i++) acc[mf][nf][i] = 0.0f;

    int wm = (wid & 1) * 64;      // 2 warps in m
    int wn = (wid >> 1) * 32;     // 4 warps in n
    int mq = lane >> 2, kq = lane & 3;

    uint32_t a_off0 = (uint32_t)(wm + (lane & 15)) * APITCH + ((lane >> 4) << 3);
    uint32_t b_krow = (uint32_t)(lane & 15);
    uint32_t b_noff = (uint32_t)(wn + ((lane >> 4) << 3));

    int NK = K / BK;
    load_stage(0); cp_commit();
    load_stage(1); cp_commit();
    cp_wait<1>();                 // stage 0 landed
    __syncthreads();
    convert_stage(0);

    for (int kt = 0; kt < NK; ++kt) {
        __syncthreads();                          // convert(kt) visible; all compute(kt-1) done
        if (kt + 2 < NK) load_stage(kt + 2);      // A slot (kt+2)%3, staging slot kt&1 (free)
        cp_commit();
        if (kt + 1 < NK) {
            cp_wait<1>();                         // group kt+1 complete
            __syncthreads();                      // staging kt+1 visible to all
            convert_stage(kt + 1);
        }
        __syncthreads();                          // f16 tile kt stable, convert(kt+1) started but
                                                  // targets other slot; A slot kt%3 ready
        uint32_t abase = aBase + (uint32_t)(kt % NASTAGE) * A_TILE_B;
        uint32_t bbase = bf16Base + (uint32_t)(kt & 1) * BF16_TILE_B;

#pragma unroll
        for (int k16 = 0; k16 < BK / 16; ++k16) {
            uint32_t af[4][4];
#pragma unroll
            for (int mf = 0; mf < 4; mf++)
                ldm4(af[mf], abase + (a_off0 + (uint32_t)(mf * 16) * APITCH) * 2
                             + (uint32_t)(k16 * 16) * 2);
            uint32_t bregs[2][4];
#pragma unroll
            for (int nb = 0; nb < 2; nb++)
                ldm4t(bregs[nb], bbase
                      + ((uint32_t)(k16 * 16 + b_krow) * BPITCH
                         + b_noff + (uint32_t)(nb * 16)) * 2);
#pragma unroll
            for (int mf = 0; mf < 4; mf++)
#pragma unroll
                for (int nf = 0; nf < 4; nf++)
                    mma16(acc[mf][nf], af[mf], &bregs[nf >> 1][(nf & 1) * 2]);
        }
    }
    __syncthreads();

    // epilogue
    const float* be = bias + (size_t)e * N + n0;
#pragma unroll
    for (int mf = 0; mf < 4; mf++) {
        int m = wm + mf * 16 + mq;
        int r0, r1;
        bool s0 = true, s1 = true;
        if (SCATTER) {
            r0 = g_tok[row0 + m];     s0 = (r0 >= 0);
            r1 = g_tok[row0 + m + 8]; s1 = (r1 >= 0);
        } else {
            r0 = row0 + m; r1 = row0 + m + 8;
        }
#pragma unroll
        for (int nf = 0; nf < 4; nf++) {
            int nc = wn + nf * 8 + kq * 2;
            float b0 = be[nc], b1 = be[nc + 1];
            float v00 = acc[mf][nf][0] + b0, v01 = acc[mf][nf][1] + b1;
            float v10 = acc[mf][nf][2] + b0, v11 = acc[mf][nf][3] + b1;
            size_t col = (size_t)n0 + nc;
            if (DO_GELU) {
                __half* Out = (__half*)OutV;
                __half2 h0 = __floats2half2_rn(gelu_exact(v00), gelu_exact(v01));
                __half2 h1 = __floats2half2_rn(gelu_exact(v10), gelu_exact(v11));
                if (s0) *(__half2*)&Out[(size_t)r0 * ldo + col] = h0;
                if (s1) *(__half2*)&Out[(size_t)r1 * ldo + col] = h1;
            } else {
                float* Out = (float*)OutV;
                if (s0) *(float2*)&Out[(size_t)r0 * ldo + col] = make_float2(v00, v01);
                if (s1) *(float2*)&Out[(size_t)r1 * ldo + col] = make_float2(v10, v11);
            }
        }
    }
}

// ---------------- launch ----------------
extern "C" void kernel_launch(void* const* d_in, const int* in_sizes, int n_in,
                              void* d_out, int out_size) {
    const float* x  = (const float*)d_in[0];
    const float* Wr = (const float*)d_in[1];
    const float* br = (const float*)d_in[2];
    const float* W1 = (const float*)d_in[3];
    const float* b1 = (const float*)d_in[4];
    const float* W2 = (const float*)d_in[5];
    const float* b2 = (const float*)d_in[6];
    const float* W3 = (const float*)d_in[7];
    const float* b3 = (const float*)d_in[8];
    float* out = (float*)d_out;

    __half *xg, *h1, *h2;
    cudaGetSymbolAddress((void**)&xg, g_xg);
    cudaGetSymbolAddress((void**)&h1, g_h1);
    cudaGetSymbolAddress((void**)&h2, g_h2);

    cudaFuncSetAttribute((const void*)moe_gemm<true, false>,
                         cudaFuncAttributeMaxDynamicSharedMemorySize, SMEM_BYTES);
    cudaFuncSetAttribute((const void*)moe_gemm<false, true>,
                         cudaFuncAttributeMaxDynamicSharedMemorySize, SMEM_BYTES);

    // routing + gather (single stream; weights consumed f32 directly by GEMMs)
    init_kernel<<<1024, 256>>>();
    router_kernel<<<T_TOK / 8, 256>>>(x, Wr, br);
    schedule_kernel<<<1, 32>>>();
    scatter_gather_kernel<<<T_TOK, 128>>>(x);

    // expert MLP
    moe_gemm<true, false><<<dim3(H1DIM / BN, MAX_TILES), 256, SMEM_BYTES>>>(
        xg, W1, b1, h1, DIM, H1DIM, H1DIM);
    moe_gemm<true, false><<<dim3(H2DIM / BN, MAX_TILES), 256, SMEM_BYTES>>>(
        h1, W2, b2, h2, H1DIM, H2DIM, H2DIM);
    moe_gemm<false, true><<<dim3(DIM / BN, MAX_TILES), 256, SMEM_BYTES>>>(
        h2, W3, b3, out, H2DIM, DIM, DIM);
}

// round 9
// speedup vs baseline: 1.0329x; 1.0329x over previous
#include <cuda_runtime.h>
#include <cuda_fp16.h>
#include <cstdint>
#include <math.h>

// ---------------- problem dims ----------------
#define T_TOK 8192
#define DIM   1024
#define NEXP  8
#define H1DIM 4096
#define H2DIM 2048
#define TPAD  9216
#define MAX_TILES 72

// ---------------- GEMM tile config ----------------
#define BM 128
#define BN 256
#define BK 32
#define NSTAGE 4
#define APITCH 40                            // halfs/row A (32+8); 20m%32 distinct
#define BPITCH 264                           // halfs/row B N-major (256+8); 4k%32 distinct
#define TILE_A_BYTES (BM * APITCH * 2)       // 10240
#define TILE_B_BYTES (BK * BPITCH * 2)       // 16896
#define STAGE_BYTES (TILE_A_BYTES + TILE_B_BYTES)   // 27136
#define SMEM_BYTES (NSTAGE * STAGE_BYTES)    // 108544 -> 1 CTA/SM (reg-fat CTA)

// ---------------- device scratch ----------------
__device__ int g_expert_id[T_TOK];
__device__ int g_counts[NEXP];
__device__ int g_cursor[NEXP];
__device__ int g_offsets[NEXP];
__device__ int g_tok[TPAD];
__device__ int g_tile_expert[MAX_TILES];
__device__ int g_tile_row[MAX_TILES];
__device__ __half g_xg[(size_t)TPAD * DIM];
__device__ __half g_h1[(size_t)TPAD * H1DIM];
__device__ __half g_h2[(size_t)TPAD * H2DIM];
__device__ __half g_wh1[(size_t)NEXP * DIM * H1DIM];    // [e][k][n], layout = W1
__device__ __half g_wh2[(size_t)NEXP * H1DIM * H2DIM];
__device__ __half g_wh3[(size_t)NEXP * H2DIM * DIM];

// ---------------- helpers ----------------
__device__ __forceinline__ void mma16(float* c, const uint32_t* a, const uint32_t* b) {
    asm volatile(
        "mma.sync.aligned.m16n8k16.row.col.f32.f16.f16.f32 "
        "{%0,%1,%2,%3}, {%4,%5,%6,%7}, {%8,%9}, {%0,%1,%2,%3};\n"
        : "+f"(c[0]), "+f"(c[1]), "+f"(c[2]), "+f"(c[3])
        : "r"(a[0]), "r"(a[1]), "r"(a[2]), "r"(a[3]), "r"(b[0]), "r"(b[1]));
}

__device__ __forceinline__ void ldm4(uint32_t* r, uint32_t addr) {
    asm volatile("ldmatrix.sync.aligned.m8n8.x4.shared.b16 {%0,%1,%2,%3}, [%4];"
                 : "=r"(r[0]), "=r"(r[1]), "=r"(r[2]), "=r"(r[3]) : "r"(addr));
}
__device__ __forceinline__ void ldm4t(uint32_t* r, uint32_t addr) {
    asm volatile("ldmatrix.sync.aligned.m8n8.x4.trans.shared.b16 {%0,%1,%2,%3}, [%4];"
                 : "=r"(r[0]), "=r"(r[1]), "=r"(r[2]), "=r"(r[3]) : "r"(addr));
}

__device__ __forceinline__ void cpa16(uint32_t smem_addr, const void* gptr) {
    asm volatile("cp.async.cg.shared.global [%0], [%1], 16;\n"
                 :: "r"(smem_addr), "l"(gptr));
}
__device__ __forceinline__ void cp_commit() { asm volatile("cp.async.commit_group;\n"); }
template <int N>
__device__ __forceinline__ void cp_wait() { asm volatile("cp.async.wait_group %0;\n" :: "n"(N)); }

__device__ __forceinline__ float gelu_exact(float v) {
    return 0.5f * v * (1.0f + erff(v * 0.70710678118654752f));
}

// ---------------- routing phases ----------------
__global__ void init_kernel() {
    size_t i = (size_t)blockIdx.x * 256 + threadIdx.x;
    if (i < TPAD) g_tok[i] = -1;
    if (i < NEXP) { g_counts[i] = 0; g_cursor[i] = 0; }
    size_t n16 = (size_t)TPAD * DIM / 8;
    for (size_t j = i; j < n16; j += (size_t)gridDim.x * 256)
        ((uint4*)g_xg)[j] = make_uint4(0, 0, 0, 0);
}

__global__ void router_kernel(const float* __restrict__ x,
                              const float* __restrict__ Wr,
                              const float* __restrict__ br) {
    __shared__ float s_wr[DIM * NEXP];
    __shared__ float s_br[NEXP];
    int tid = threadIdx.x;
    for (int i = tid; i < DIM * NEXP / 4; i += 256)
        ((float4*)s_wr)[i] = ((const float4*)Wr)[i];
    if (tid < NEXP) s_br[tid] = br[tid];
    __syncthreads();

    int warp = tid >> 5, lane = tid & 31;
    int t = blockIdx.x * 8 + warp;

    float acc[NEXP];
#pragma unroll
    for (int e = 0; e < NEXP; e++) acc[e] = 0.0f;
    const float* xr = x + (size_t)t * DIM;
    for (int d = lane; d < DIM; d += 32) {
        float xv = xr[d];
#pragma unroll
        for (int e = 0; e < NEXP; e++) acc[e] += xv * s_wr[d * NEXP + e];
    }
#pragma unroll
    for (int e = 0; e < NEXP; e++)
        for (int o = 16; o; o >>= 1) acc[e] += __shfl_down_sync(0xffffffffu, acc[e], o);

    if (lane == 0) {
        float best = acc[0] + s_br[0];
        int bi = 0;
        for (int e = 1; e < NEXP; e++) {
            float v = acc[e] + s_br[e];
            if (v > best) { best = v; bi = e; }   // first-max == jnp.argmax
        }
        g_expert_id[t] = bi;
        atomicAdd(&g_counts[bi], 1);
    }
}

__global__ void schedule_kernel() {
    if (threadIdx.x == 0 && blockIdx.x == 0) {
        int off = 0, t = 0;
        for (int e = 0; e < NEXP; e++) {
            g_offsets[e] = off;
            int c = g_counts[e];
            int tiles = (c + BM - 1) >> 7;
            for (int i = 0; i < tiles; i++) {
                g_tile_expert[t] = e;
                g_tile_row[t] = off + i * BM;
                t++;
            }
            off += tiles << 7;
        }
        for (; t < MAX_TILES; t++) { g_tile_expert[t] = -1; g_tile_row[t] = 0; }
    }
}

// fused scatter + gather + f16 convert: one block per token
__global__ void scatter_gather_kernel(const float* __restrict__ x) {
    __shared__ int s_pos;
    int t = blockIdx.x;
    if (threadIdx.x == 0) {
        int e = g_expert_id[t];
        int pos = g_offsets[e] + atomicAdd(&g_cursor[e], 1);
        g_tok[pos] = t;
        s_pos = pos;
    }
    __syncthreads();
    int pos = s_pos;
    const float4* xr = (const float4*)(x + (size_t)t * DIM);
    uint2* orow = (uint2*)(g_xg + (size_t)pos * DIM);
#pragma unroll
    for (int i = 0; i < 2; i++) {
        int c = threadIdx.x + i * 128;
        float4 v = xr[c];
        __half2 h0 = __floats2half2_rn(v.x, v.y);
        __half2 h1 = __floats2half2_rn(v.z, v.w);
        orow[c] = make_uint2(*(uint32_t*)&h0, *(uint32_t*)&h1);
    }
}

// streaming f32 -> f16 convert, layout preserved
__global__ void convert_w(const float* __restrict__ W, __half* __restrict__ Wh,
                          size_t n8) {
    size_t i = (size_t)blockIdx.x * 256 + threadIdx.x;
    if (i >= n8) return;
    float4 a = ((const float4*)W)[i * 2];
    float4 b = ((const float4*)W)[i * 2 + 1];
    __half2 h0 = __floats2half2_rn(a.x, a.y);
    __half2 h1 = __floats2half2_rn(a.z, a.w);
    __half2 h2 = __floats2half2_rn(b.x, b.y);
    __half2 h3 = __floats2half2_rn(b.z, b.w);
    uint4 o;
    o.x = *(uint32_t*)&h0; o.y = *(uint32_t*)&h1;
    o.z = *(uint32_t*)&h2; o.w = *(uint32_t*)&h3;
    ((uint4*)Wh)[i] = o;
}

// ---------------- grouped GEMM: fp16 mma, CTA 128x256, warp 64x64 -----------
// A [rows][K] fp16 K-major.  B = Wh [E][K][N] fp16 N-major (ldmatrix.trans).
// 8 warps (2 m x 4 n), BK=32, 4-stage cp.async ring, 1 CTA/SM (reg-fat).
template <bool DO_GELU, bool SCATTER>
__global__ void __launch_bounds__(256)
moe_gemm(const __half* __restrict__ A, const __half* __restrict__ Wh,
         const float* __restrict__ bias, void* __restrict__ OutV,
         int K, int N, int ldo) {
    int e = g_tile_expert[blockIdx.y];
    if (e < 0) return;
    int row0 = g_tile_row[blockIdx.y];
    int n0 = blockIdx.x * BN;

    extern __shared__ __half smem[];
    int tid = threadIdx.x;
    int wid = tid >> 5, lane = tid & 31;

    const __half* Ap = A + (size_t)row0 * K;
    const __half* Bp = Wh + (size_t)e * K * N + n0;    // k-row stride = N

    uint32_t smem_u = (uint32_t)__cvta_generic_to_shared(smem);

    // per stage: A 128 rows x 4 chunks(16B) = 512; B 32 rows x 32 chunks = 1024
    auto load_stage = [&](int j) {
        uint32_t base = smem_u + (uint32_t)(j % NSTAGE) * STAGE_BYTES;
        int kk = j * BK;
#pragma unroll
        for (int i = 0; i < 6; i++) {
            int c = tid + i * 256;
            if (c < 512) {                       // A: K-major rows
                int r = c >> 2, c4 = c & 3;
                cpa16(base + (uint32_t)(r * APITCH + c4 * 8) * 2,
                      Ap + (size_t)r * K + kk + c4 * 8);
            } else {                             // B: N-major k-rows (512B each)
                int cb = c - 512;
                int r = cb >> 5, c8 = cb & 31;
                cpa16(base + TILE_A_BYTES + (uint32_t)(r * BPITCH + c8 * 8) * 2,
                      Bp + (size_t)(kk + r) * N + c8 * 8);
            }
        }
    };

    float acc[4][8][4];
#pragma unroll
    for (int mf = 0; mf < 4; mf++)
#pragma unroll
        for (int nf = 0; nf < 8; nf++)
#pragma unroll
            for (int i = 0; i < 4; i++) acc[mf][nf][i] = 0.0f;

    int wm = (wid & 1) * 64;      // 2 warps in m
    int wn = (wid >> 1) * 64;     // 4 warps in n, 64-wide tiles
    int mq = lane >> 2, kq = lane & 3;

    uint32_t a_off0 = (uint32_t)(wm + (lane & 15)) * APITCH + ((lane >> 4) << 3);
    uint32_t b_krow = (uint32_t)(lane & 15);
    uint32_t b_noff = (uint32_t)(wn + ((lane >> 4) << 3));

    int NK = K / BK;
    load_stage(0); cp_commit();
    load_stage(1); cp_commit();
    load_stage(2); cp_commit();

    for (int kt = 0; kt < NK; ++kt) {
        cp_wait<2>();                 // stage kt landed (2 newer groups may fly)
        __syncthreads();              // also: all warps finished stage kt-1 compute

        if (kt + 3 < NK) load_stage(kt + 3);   // slot (kt+3)%4 == (kt-1)%4, free
        cp_commit();

        uint32_t abase = smem_u + (uint32_t)(kt % NSTAGE) * STAGE_BYTES;
        uint32_t bbase = abase + TILE_A_BYTES;

#pragma unroll
        for (int k16 = 0; k16 < BK / 16; ++k16) {
            uint32_t koff = (uint32_t)(k16 * 16) * 2;
            uint32_t bf[4][4];
#pragma unroll
            for (int nb = 0; nb < 4; nb++)
                ldm4t(bf[nb], bbase
                      + ((uint32_t)(k16 * 16 + b_krow) * BPITCH
                         + b_noff + (uint32_t)(nb * 16)) * 2);
#pragma unroll
            for (int mf = 0; mf < 4; mf++) {
                uint32_t af[4];
                ldm4(af, abase + (a_off0 + (uint32_t)(mf * 16) * APITCH) * 2 + koff);
#pragma unroll
                for (int nf = 0; nf < 8; nf++)
                    mma16(acc[mf][nf], af, &bf[nf >> 1][(nf & 1) * 2]);
            }
        }
    }
    __syncthreads();

    // epilogue
    const float* be = bias + (size_t)e * N + n0;
#pragma unroll
    for (int mf = 0; mf < 4; mf++) {
        int m = wm + mf * 16 + mq;
        int r0, r1;
        bool s0 = true, s1 = true;
        if (SCATTER) {
            r0 = g_tok[row0 + m];     s0 = (r0 >= 0);
            r1 = g_tok[row0 + m + 8]; s1 = (r1 >= 0);
        } else {
            r0 = row0 + m; r1 = row0 + m + 8;
        }
#pragma unroll
        for (int nf = 0; nf < 8; nf++) {
            int nc = wn + nf * 8 + kq * 2;
            float b0 = be[nc], b1 = be[nc + 1];
            float v00 = acc[mf][nf][0] + b0, v01 = acc[mf][nf][1] + b1;
            float v10 = acc[mf][nf][2] + b0, v11 = acc[mf][nf][3] + b1;
            size_t col = (size_t)n0 + nc;
            if (DO_GELU) {
                __half* Out = (__half*)OutV;
                __half2 h0 = __floats2half2_rn(gelu_exact(v00), gelu_exact(v01));
                __half2 h1 = __floats2half2_rn(gelu_exact(v10), gelu_exact(v11));
                if (s0) *(__half2*)&Out[(size_t)r0 * ldo + col] = h0;
                if (s1) *(__half2*)&Out[(size_t)r1 * ldo + col] = h1;
            } else {
                float* Out = (float*)OutV;
                if (s0) *(float2*)&Out[(size_t)r0 * ldo + col] = make_float2(v00, v01);
                if (s1) *(float2*)&Out[(size_t)r1 * ldo + col] = make_float2(v10, v11);
            }
        }
    }
}

// ---------------- launch ----------------
extern "C" void kernel_launch(void* const* d_in, const int* in_sizes, int n_in,
                              void* d_out, int out_size) {
    const float* x  = (const float*)d_in[0];
    const float* Wr = (const float*)d_in[1];
    const float* br = (const float*)d_in[2];
    const float* W1 = (const float*)d_in[3];
    const float* b1 = (const float*)d_in[4];
    const float* W2 = (const float*)d_in[5];
    const float* b2 = (const float*)d_in[6];
    const float* W3 = (const float*)d_in[7];
    const float* b3 = (const float*)d_in[8];
    float* out = (float*)d_out;

    __half *xg, *h1, *h2, *wh1, *wh2, *wh3;
    cudaGetSymbolAddress((void**)&xg, g_xg);
    cudaGetSymbolAddress((void**)&h1, g_h1);
    cudaGetSymbolAddress((void**)&h2, g_h2);
    cudaGetSymbolAddress((void**)&wh1, g_wh1);
    cudaGetSymbolAddress((void**)&wh2, g_wh2);
    cudaGetSymbolAddress((void**)&wh3, g_wh3);

    cudaFuncSetAttribute((const void*)moe_gemm<true, false>,
                         cudaFuncAttributeMaxDynamicSharedMemorySize, SMEM_BYTES);
    cudaFuncSetAttribute((const void*)moe_gemm<false, true>,
                         cudaFuncAttributeMaxDynamicSharedMemorySize, SMEM_BYTES);

    // routing + gather
    init_kernel<<<1024, 256>>>();
    router_kernel<<<T_TOK / 8, 256>>>(x, Wr, br);
    schedule_kernel<<<1, 32>>>();
    scatter_gather_kernel<<<T_TOK, 128>>>(x);

    // weight convert prepass (serial; overlap measured neutral in R7)
    size_t n1 = (size_t)NEXP * DIM * H1DIM / 8;
    size_t n2 = (size_t)NEXP * H1DIM * H2DIM / 8;
    size_t n3 = (size_t)NEXP * H2DIM * DIM / 8;
    convert_w<<<(unsigned)((n1 + 255) / 256), 256>>>(W1, wh1, n1);
    convert_w<<<(unsigned)((n2 + 255) / 256), 256>>>(W2, wh2, n2);
    convert_w<<<(unsigned)((n3 + 255) / 256), 256>>>(W3, wh3, n3);

    // expert MLP
    moe_gemm<true, false><<<dim3(H1DIM / BN, MAX_TILES), 256, SMEM_BYTES>>>(
        xg, wh1, b1, h1, DIM, H1DIM, H1DIM);
    moe_gemm<true, false><<<dim3(H2DIM / BN, MAX_TILES), 256, SMEM_BYTES>>>(
        h1, wh2, b2, h2, H1DIM, H2DIM, H2DIM);
    moe_gemm<false, true><<<dim3(DIM / BN, MAX_TILES), 256, SMEM_BYTES>>>(
        h2, wh3, b3, out, H2DIM, DIM, DIM);
}

// round 10
// speedup vs baseline: 1.1431x; 1.1067x over previous
#include <cuda_runtime.h>
#include <cuda_fp16.h>
#include <cstdint>
#include <math.h>

// ---------------- problem dims ----------------
#define T_TOK 8192
#define DIM   1024
#define NEXP  8
#define H1DIM 4096
#define H2DIM 2048
#define TPAD  9216
#define MAX_TILES 72

// ---------------- GEMM tile config ----------------
#define BM 128
#define BN 256
#define BK 64
#define NTHREADS 512
#define NSTAGE 3
#define APITCH 72                            // halfs/row A K-major (64+8); proven R6
#define BPITCH 264                           // halfs/row B N-major (256+8); 4k%32 distinct
#define TILE_A_BYTES (BM * APITCH * 2)       // 18432
#define TILE_B_BYTES (BK * BPITCH * 2)       // 33792
#define STAGE_BYTES (TILE_A_BYTES + TILE_B_BYTES)   // 52224
#define SMEM_BYTES (NSTAGE * STAGE_BYTES)    // 156672 -> 1 CTA/SM, 16 warps

// ---------------- device scratch ----------------
__device__ int g_expert_id[T_TOK];
__device__ int g_counts[NEXP];
__device__ int g_cursor[NEXP];
__device__ int g_offsets[NEXP];
__device__ int g_tok[TPAD];
__device__ int g_tile_expert[MAX_TILES];
__device__ int g_tile_row[MAX_TILES];
__device__ __half g_xg[(size_t)TPAD * DIM];
__device__ __half g_h1[(size_t)TPAD * H1DIM];
__device__ __half g_h2[(size_t)TPAD * H2DIM];
__device__ __half g_wh1[(size_t)NEXP * DIM * H1DIM];    // [e][k][n], layout = W1
__device__ __half g_wh2[(size_t)NEXP * H1DIM * H2DIM];
__device__ __half g_wh3[(size_t)NEXP * H2DIM * DIM];

// ---------------- helpers ----------------
__device__ __forceinline__ void mma16(float* c, const uint32_t* a, const uint32_t* b) {
    asm volatile(
        "mma.sync.aligned.m16n8k16.row.col.f32.f16.f16.f32 "
        "{%0,%1,%2,%3}, {%4,%5,%6,%7}, {%8,%9}, {%0,%1,%2,%3};\n"
        : "+f"(c[0]), "+f"(c[1]), "+f"(c[2]), "+f"(c[3])
        : "r"(a[0]), "r"(a[1]), "r"(a[2]), "r"(a[3]), "r"(b[0]), "r"(b[1]));
}

__device__ __forceinline__ void ldm4(uint32_t* r, uint32_t addr) {
    asm volatile("ldmatrix.sync.aligned.m8n8.x4.shared.b16 {%0,%1,%2,%3}, [%4];"
                 : "=r"(r[0]), "=r"(r[1]), "=r"(r[2]), "=r"(r[3]) : "r"(addr));
}
__device__ __forceinline__ void ldm4t(uint32_t* r, uint32_t addr) {
    asm volatile("ldmatrix.sync.aligned.m8n8.x4.trans.shared.b16 {%0,%1,%2,%3}, [%4];"
                 : "=r"(r[0]), "=r"(r[1]), "=r"(r[2]), "=r"(r[3]) : "r"(addr));
}

__device__ __forceinline__ void cpa16(uint32_t smem_addr, const void* gptr) {
    asm volatile("cp.async.cg.shared.global [%0], [%1], 16;\n"
                 :: "r"(smem_addr), "l"(gptr));
}
__device__ __forceinline__ void cp_commit() { asm volatile("cp.async.commit_group;\n"); }
template <int N>
__device__ __forceinline__ void cp_wait() { asm volatile("cp.async.wait_group %0;\n" :: "n"(N)); }

__device__ __forceinline__ float gelu_exact(float v) {
    return 0.5f * v * (1.0f + erff(v * 0.70710678118654752f));
}

// ---------------- routing phases ----------------
__global__ void init_kernel() {
    size_t i = (size_t)blockIdx.x * 256 + threadIdx.x;
    if (i < TPAD) g_tok[i] = -1;
    if (i < NEXP) { g_counts[i] = 0; g_cursor[i] = 0; }
    size_t n16 = (size_t)TPAD * DIM / 8;
    for (size_t j = i; j < n16; j += (size_t)gridDim.x * 256)
        ((uint4*)g_xg)[j] = make_uint4(0, 0, 0, 0);
}

__global__ void router_kernel(const float* __restrict__ x,
                              const float* __restrict__ Wr,
                              const float* __restrict__ br) {
    __shared__ float s_wr[DIM * NEXP];
    __shared__ float s_br[NEXP];
    int tid = threadIdx.x;
    for (int i = tid; i < DIM * NEXP / 4; i += 256)
        ((float4*)s_wr)[i] = ((const float4*)Wr)[i];
    if (tid < NEXP) s_br[tid] = br[tid];
    __syncthreads();

    int warp = tid >> 5, lane = tid & 31;
    int t = blockIdx.x * 8 + warp;

    float acc[NEXP];
#pragma unroll
    for (int e = 0; e < NEXP; e++) acc[e] = 0.0f;
    const float* xr = x + (size_t)t * DIM;
    for (int d = lane; d < DIM; d += 32) {
        float xv = xr[d];
#pragma unroll
        for (int e = 0; e < NEXP; e++) acc[e] += xv * s_wr[d * NEXP + e];
    }
#pragma unroll
    for (int e = 0; e < NEXP; e++)
        for (int o = 16; o; o >>= 1) acc[e] += __shfl_down_sync(0xffffffffu, acc[e], o);

    if (lane == 0) {
        float best = acc[0] + s_br[0];
        int bi = 0;
        for (int e = 1; e < NEXP; e++) {
            float v = acc[e] + s_br[e];
            if (v > best) { best = v; bi = e; }   // first-max == jnp.argmax
        }
        g_expert_id[t] = bi;
        atomicAdd(&g_counts[bi], 1);
    }
}

__global__ void schedule_kernel() {
    if (threadIdx.x == 0 && blockIdx.x == 0) {
        int off = 0, t = 0;
        for (int e = 0; e < NEXP; e++) {
            g_offsets[e] = off;
            int c = g_counts[e];
            int tiles = (c + BM - 1) >> 7;
            for (int i = 0; i < tiles; i++) {
                g_tile_expert[t] = e;
                g_tile_row[t] = off + i * BM;
                t++;
            }
            off += tiles << 7;
        }
        for (; t < MAX_TILES; t++) { g_tile_expert[t] = -1; g_tile_row[t] = 0; }
    }
}

// fused scatter + gather + f16 convert: one block per token
__global__ void scatter_gather_kernel(const float* __restrict__ x) {
    __shared__ int s_pos;
    int t = blockIdx.x;
    if (threadIdx.x == 0) {
        int e = g_expert_id[t];
        int pos = g_offsets[e] + atomicAdd(&g_cursor[e], 1);
        g_tok[pos] = t;
        s_pos = pos;
    }
    __syncthreads();
    int pos = s_pos;
    const float4* xr = (const float4*)(x + (size_t)t * DIM);
    uint2* orow = (uint2*)(g_xg + (size_t)pos * DIM);
#pragma unroll
    for (int i = 0; i < 2; i++) {
        int c = threadIdx.x + i * 128;
        float4 v = xr[c];
        __half2 h0 = __floats2half2_rn(v.x, v.y);
        __half2 h1 = __floats2half2_rn(v.z, v.w);
        orow[c] = make_uint2(*(uint32_t*)&h0, *(uint32_t*)&h1);
    }
}

// streaming f32 -> f16 convert, layout preserved
__global__ void convert_w(const float* __restrict__ W, __half* __restrict__ Wh,
                          size_t n8) {
    size_t i = (size_t)blockIdx.x * 256 + threadIdx.x;
    if (i >= n8) return;
    float4 a = ((const float4*)W)[i * 2];
    float4 b = ((const float4*)W)[i * 2 + 1];
    __half2 h0 = __floats2half2_rn(a.x, a.y);
    __half2 h1 = __floats2half2_rn(a.z, a.w);
    __half2 h2 = __floats2half2_rn(b.x, b.y);
    __half2 h3 = __floats2half2_rn(b.z, b.w);
    uint4 o;
    o.x = *(uint32_t*)&h0; o.y = *(uint32_t*)&h1;
    o.z = *(uint32_t*)&h2; o.w = *(uint32_t*)&h3;
    ((uint4*)Wh)[i] = o;
}

// ---------------- grouped GEMM: fp16 mma, CTA 128x256, 16 warps of 64x32 ----
// A [rows][K] fp16 K-major.  B = Wh [E][K][N] fp16 N-major (ldmatrix.trans).
// 512 threads: 2 m-warps x 8 n-warps; BK=64, 3-stage cp.async; 4 warps/SMSP.
template <bool DO_GELU, bool SCATTER>
__global__ void __launch_bounds__(NTHREADS, 1)
moe_gemm(const __half* __restrict__ A, const __half* __restrict__ Wh,
         const float* __restrict__ bias, void* __restrict__ OutV,
         int K, int N, int ldo) {
    int e = g_tile_expert[blockIdx.y];
    if (e < 0) return;
    int row0 = g_tile_row[blockIdx.y];
    int n0 = blockIdx.x * BN;

    extern __shared__ __half smem[];
    int tid = threadIdx.x;
    int wid = tid >> 5, lane = tid & 31;

    const __half* Ap = A + (size_t)row0 * K;
    const __half* Bp = Wh + (size_t)e * K * N + n0;    // k-row stride = N

    uint32_t smem_u = (uint32_t)__cvta_generic_to_shared(smem);

    // per stage: A 128 rows x 8 chunks(16B) = 1024; B 64 rows x 32 chunks = 2048
    // -> 3072 chunks / 512 threads = 6 each
    auto load_stage = [&](int j) {
        uint32_t base = smem_u + (uint32_t)(j % NSTAGE) * STAGE_BYTES;
        int kk = j * BK;
#pragma unroll
        for (int i = 0; i < 6; i++) {
            int c = tid + i * NTHREADS;
            if (c < 1024) {                      // A: K-major rows
                int r = c >> 3, c8 = c & 7;
                cpa16(base + (uint32_t)(r * APITCH + c8 * 8) * 2,
                      Ap + (size_t)r * K + kk + c8 * 8);
            } else {                             // B: N-major k-rows (512B each)
                int cb = c - 1024;
                int r = cb >> 5, c8 = cb & 31;
                cpa16(base + TILE_A_BYTES + (uint32_t)(r * BPITCH + c8 * 8) * 2,
                      Bp + (size_t)(kk + r) * N + c8 * 8);
            }
        }
    };

    float acc[4][4][4];
#pragma unroll
    for (int mf = 0; mf < 4; mf++)
#pragma unroll
        for (int nf = 0; nf < 4; nf++)
#pragma unroll
            for (int i = 0; i < 4; i++) acc[mf][nf][i] = 0.0f;

    int wm = (wid & 1) * 64;      // 2 warps in m
    int wn = (wid >> 1) * 32;     // 8 warps in n
    int mq = lane >> 2, kq = lane & 3;

    uint32_t a_off0 = (uint32_t)(wm + (lane & 15)) * APITCH + ((lane >> 4) << 3);
    uint32_t b_krow = (uint32_t)(lane & 15);
    uint32_t b_noff = (uint32_t)(wn + ((lane >> 4) << 3));

    int NK = K / BK;
    load_stage(0); cp_commit();
    load_stage(1); cp_commit();

    for (int kt = 0; kt < NK; ++kt) {
        cp_wait<1>();
        __syncthreads();

        if (kt + 2 < NK) load_stage(kt + 2);
        cp_commit();

        uint32_t abase = smem_u + (uint32_t)(kt % NSTAGE) * STAGE_BYTES;
        uint32_t bbase = abase + TILE_A_BYTES;

#pragma unroll
        for (int k16 = 0; k16 < BK / 16; ++k16) {
            uint32_t koff = (uint32_t)(k16 * 16) * 2;
            uint32_t af[4][4];
#pragma unroll
            for (int mf = 0; mf < 4; mf++)
                ldm4(af[mf], abase + (a_off0 + (uint32_t)(mf * 16) * APITCH) * 2 + koff);
            uint32_t bregs[2][4];
#pragma unroll
            for (int nb = 0; nb < 2; nb++)
                ldm4t(bregs[nb], bbase
                      + ((uint32_t)(k16 * 16 + b_krow) * BPITCH
                         + b_noff + (uint32_t)(nb * 16)) * 2);
#pragma unroll
            for (int mf = 0; mf < 4; mf++)
#pragma unroll
                for (int nf = 0; nf < 4; nf++)
                    mma16(acc[mf][nf], af[mf], &bregs[nf >> 1][(nf & 1) * 2]);
        }
    }
    __syncthreads();

    // epilogue
    const float* be = bias + (size_t)e * N + n0;
#pragma unroll
    for (int mf = 0; mf < 4; mf++) {
        int m = wm + mf * 16 + mq;
        int r0, r1;
        bool s0 = true, s1 = true;
        if (SCATTER) {
            r0 = g_tok[row0 + m];     s0 = (r0 >= 0);
            r1 = g_tok[row0 + m + 8]; s1 = (r1 >= 0);
        } else {
            r0 = row0 + m; r1 = row0 + m + 8;
        }
#pragma unroll
        for (int nf = 0; nf < 4; nf++) {
            int nc = wn + nf * 8 + kq * 2;
            float b0 = be[nc], b1 = be[nc + 1];
            float v00 = acc[mf][nf][0] + b0, v01 = acc[mf][nf][1] + b1;
            float v10 = acc[mf][nf][2] + b0, v11 = acc[mf][nf][3] + b1;
            size_t col = (size_t)n0 + nc;
            if (DO_GELU) {
                __half* Out = (__half*)OutV;
                __half2 h0 = __floats2half2_rn(gelu_exact(v00), gelu_exact(v01));
                __half2 h1 = __floats2half2_rn(gelu_exact(v10), gelu_exact(v11));
                if (s0) *(__half2*)&Out[(size_t)r0 * ldo + col] = h0;
                if (s1) *(__half2*)&Out[(size_t)r1 * ldo + col] = h1;
            } else {
                float* Out = (float*)OutV;
                if (s0) *(float2*)&Out[(size_t)r0 * ldo + col] = make_float2(v00, v01);
                if (s1) *(float2*)&Out[(size_t)r1 * ldo + col] = make_float2(v10, v11);
            }
        }
    }
}

// ---------------- launch ----------------
extern "C" void kernel_launch(void* const* d_in, const int* in_sizes, int n_in,
                              void* d_out, int out_size) {
    const float* x  = (const float*)d_in[0];
    const float* Wr = (const float*)d_in[1];
    const float* br = (const float*)d_in[2];
    const float* W1 = (const float*)d_in[3];
    const float* b1 = (const float*)d_in[4];
    const float* W2 = (const float*)d_in[5];
    const float* b2 = (const float*)d_in[6];
    const float* W3 = (const float*)d_in[7];
    const float* b3 = (const float*)d_in[8];
    float* out = (float*)d_out;

    __half *xg, *h1, *h2, *wh1, *wh2, *wh3;
    cudaGetSymbolAddress((void**)&xg, g_xg);
    cudaGetSymbolAddress((void**)&h1, g_h1);
    cudaGetSymbolAddress((void**)&h2, g_h2);
    cudaGetSymbolAddress((void**)&wh1, g_wh1);
    cudaGetSymbolAddress((void**)&wh2, g_wh2);
    cudaGetSymbolAddress((void**)&wh3, g_wh3);

    cudaFuncSetAttribute((const void*)moe_gemm<true, false>,
                         cudaFuncAttributeMaxDynamicSharedMemorySize, SMEM_BYTES);
    cudaFuncSetAttribute((const void*)moe_gemm<false, true>,
                         cudaFuncAttributeMaxDynamicSharedMemorySize, SMEM_BYTES);

    // routing + gather
    init_kernel<<<1024, 256>>>();
    router_kernel<<<T_TOK / 8, 256>>>(x, Wr, br);
    schedule_kernel<<<1, 32>>>();
    scatter_gather_kernel<<<T_TOK, 128>>>(x);

    // weight convert prepass
    size_t n1 = (size_t)NEXP * DIM * H1DIM / 8;
    size_t n2 = (size_t)NEXP * H1DIM * H2DIM / 8;
    size_t n3 = (size_t)NEXP * H2DIM * DIM / 8;
    convert_w<<<(unsigned)((n1 + 255) / 256), 256>>>(W1, wh1, n1);
    convert_w<<<(unsigned)((n2 + 255) / 256), 256>>>(W2, wh2, n2);
    convert_w<<<(unsigned)((n3 + 255) / 256), 256>>>(W3, wh3, n3);

    // expert MLP
    moe_gemm<true, false><<<dim3(H1DIM / BN, MAX_TILES), NTHREADS, SMEM_BYTES>>>(
        xg, wh1, b1, h1, DIM, H1DIM, H1DIM);
    moe_gemm<true, false><<<dim3(H2DIM / BN, MAX_TILES), NTHREADS, SMEM_BYTES>>>(
        h1, wh2, b2, h2, H1DIM, H2DIM, H2DIM);
    moe_gemm<false, true><<<dim3(DIM / BN, MAX_TILES), NTHREADS, SMEM_BYTES>>>(
        h2, wh3, b3, out, H2DIM, DIM, DIM);
}

// round 11
// speedup vs baseline: 1.1690x; 1.0227x over previous
#include <cuda_runtime.h>
#include <cuda_fp16.h>
#include <cstdint>
#include <math.h>

// ---------------- problem dims ----------------
#define T_TOK 8192
#define DIM   1024
#define NEXP  8
#define H1DIM 4096
#define H2DIM 2048
#define TPAD  9216
#define MAX_TILES 72

// ---------------- GEMM tile config (R6 champion) ----------------
#define BM 128
#define BN 128
#define BK 64
#define NSTAGE 3
#define APITCH 72                            // halfs/row A K-major
#define BPITCH 136                           // halfs/row B N-major
#define TILE_A_BYTES (BM * APITCH * 2)       // 18432
#define TILE_B_BYTES (BK * BPITCH * 2)       // 17408
#define STAGE_BYTES (TILE_A_BYTES + TILE_B_BYTES)   // 35840
#define SMEM_BYTES (NSTAGE * STAGE_BYTES)    // 107520 -> 2 CTAs/SM

// ---------------- device scratch ----------------
__device__ int g_expert_id[T_TOK];
__device__ int g_counts[NEXP];
__device__ int g_cursor[NEXP];
__device__ int g_offsets[NEXP];
__device__ int g_tok[TPAD];
__device__ int g_tile_expert[MAX_TILES];
__device__ int g_tile_row[MAX_TILES];
__device__ __half g_xg[(size_t)TPAD * DIM];
__device__ __half g_h1[(size_t)TPAD * H1DIM];
__device__ __half g_h2[(size_t)TPAD * H2DIM];
__device__ __half g_wh1[(size_t)NEXP * DIM * H1DIM];    // [e][k][n], layout = W1
__device__ __half g_wh2[(size_t)NEXP * H1DIM * H2DIM];
__device__ __half g_wh3[(size_t)NEXP * H2DIM * DIM];

// ---------------- helpers ----------------
__device__ __forceinline__ void mma16(float* c, const uint32_t* a, const uint32_t* b) {
    asm volatile(
        "mma.sync.aligned.m16n8k16.row.col.f32.f16.f16.f32 "
        "{%0,%1,%2,%3}, {%4,%5,%6,%7}, {%8,%9}, {%0,%1,%2,%3};\n"
        : "+f"(c[0]), "+f"(c[1]), "+f"(c[2]), "+f"(c[3])
        : "r"(a[0]), "r"(a[1]), "r"(a[2]), "r"(a[3]), "r"(b[0]), "r"(b[1]));
}

__device__ __forceinline__ void ldm4(uint32_t* r, uint32_t addr) {
    asm volatile("ldmatrix.sync.aligned.m8n8.x4.shared.b16 {%0,%1,%2,%3}, [%4];"
                 : "=r"(r[0]), "=r"(r[1]), "=r"(r[2]), "=r"(r[3]) : "r"(addr));
}
__device__ __forceinline__ void ldm4t(uint32_t* r, uint32_t addr) {
    asm volatile("ldmatrix.sync.aligned.m8n8.x4.trans.shared.b16 {%0,%1,%2,%3}, [%4];"
                 : "=r"(r[0]), "=r"(r[1]), "=r"(r[2]), "=r"(r[3]) : "r"(addr));
}

__device__ __forceinline__ void cpa16(uint32_t smem_addr, const void* gptr) {
    asm volatile("cp.async.cg.shared.global [%0], [%1], 16;\n"
                 :: "r"(smem_addr), "l"(gptr));
}
__device__ __forceinline__ void cp_commit() { asm volatile("cp.async.commit_group;\n"); }
template <int N>
__device__ __forceinline__ void cp_wait() { asm volatile("cp.async.wait_group %0;\n" :: "n"(N)); }

__device__ __forceinline__ float gelu_exact(float v) {
    return 0.5f * v * (1.0f + erff(v * 0.70710678118654752f));
}

// ---------------- routing phases ----------------
__global__ void init_kernel() {
    size_t i = (size_t)blockIdx.x * 256 + threadIdx.x;
    if (i < TPAD) g_tok[i] = -1;
    if (i < NEXP) { g_counts[i] = 0; g_cursor[i] = 0; }
    size_t n16 = (size_t)TPAD * DIM / 8;
    for (size_t j = i; j < n16; j += (size_t)gridDim.x * 256)
        ((uint4*)g_xg)[j] = make_uint4(0, 0, 0, 0);
}

__global__ void router_kernel(const float* __restrict__ x,
                              const float* __restrict__ Wr,
                              const float* __restrict__ br) {
    __shared__ float s_wr[DIM * NEXP];
    __shared__ float s_br[NEXP];
    int tid = threadIdx.x;
    for (int i = tid; i < DIM * NEXP / 4; i += 256)
        ((float4*)s_wr)[i] = ((const float4*)Wr)[i];
    if (tid < NEXP) s_br[tid] = br[tid];
    __syncthreads();

    int warp = tid >> 5, lane = tid & 31;
    int t = blockIdx.x * 8 + warp;

    float acc[NEXP];
#pragma unroll
    for (int e = 0; e < NEXP; e++) acc[e] = 0.0f;
    const float* xr = x + (size_t)t * DIM;
    for (int d = lane; d < DIM; d += 32) {
        float xv = xr[d];
#pragma unroll
        for (int e = 0; e < NEXP; e++) acc[e] += xv * s_wr[d * NEXP + e];
    }
#pragma unroll
    for (int e = 0; e < NEXP; e++)
        for (int o = 16; o; o >>= 1) acc[e] += __shfl_down_sync(0xffffffffu, acc[e], o);

    if (lane == 0) {
        float best = acc[0] + s_br[0];
        int bi = 0;
        for (int e = 1; e < NEXP; e++) {
            float v = acc[e] + s_br[e];
            if (v > best) { best = v; bi = e; }   // first-max == jnp.argmax
        }
        g_expert_id[t] = bi;
        atomicAdd(&g_counts[bi], 1);
    }
}

__global__ void schedule_kernel() {
    if (threadIdx.x == 0 && blockIdx.x == 0) {
        int off = 0, t = 0;
        for (int e = 0; e < NEXP; e++) {
            g_offsets[e] = off;
            int c = g_counts[e];
            int tiles = (c + BM - 1) >> 7;
            for (int i = 0; i < tiles; i++) {
                g_tile_expert[t] = e;
                g_tile_row[t] = off + i * BM;
                t++;
            }
            off += tiles << 7;
        }
        for (; t < MAX_TILES; t++) { g_tile_expert[t] = -1; g_tile_row[t] = 0; }
    }
}

// fused scatter + gather + f16 convert: one block per token
__global__ void scatter_gather_kernel(const float* __restrict__ x) {
    __shared__ int s_pos;
    int t = blockIdx.x;
    if (threadIdx.x == 0) {
        int e = g_expert_id[t];
        int pos = g_offsets[e] + atomicAdd(&g_cursor[e], 1);
        g_tok[pos] = t;
        s_pos = pos;
    }
    __syncthreads();
    int pos = s_pos;
    const float4* xr = (const float4*)(x + (size_t)t * DIM);
    uint2* orow = (uint2*)(g_xg + (size_t)pos * DIM);
#pragma unroll
    for (int i = 0; i < 2; i++) {
        int c = threadIdx.x + i * 128;
        float4 v = xr[c];
        __half2 h0 = __floats2half2_rn(v.x, v.y);
        __half2 h1 = __floats2half2_rn(v.z, v.w);
        orow[c] = make_uint2(*(uint32_t*)&h0, *(uint32_t*)&h1);
    }
}

// streaming f32 -> f16 convert, full-throughput (one item per thread)
__global__ void convert_w(const float* __restrict__ W, __half* __restrict__ Wh,
                          size_t n8) {
    size_t i = (size_t)blockIdx.x * 256 + threadIdx.x;
    if (i >= n8) return;
    float4 a = ((const float4*)W)[i * 2];
    float4 b = ((const float4*)W)[i * 2 + 1];
    __half2 h0 = __floats2half2_rn(a.x, a.y);
    __half2 h1 = __floats2half2_rn(a.z, a.w);
    __half2 h2 = __floats2half2_rn(b.x, b.y);
    __half2 h3 = __floats2half2_rn(b.z, b.w);
    uint4 o;
    o.x = *(uint32_t*)&h0; o.y = *(uint32_t*)&h1;
    o.z = *(uint32_t*)&h2; o.w = *(uint32_t*)&h3;
    ((uint4*)Wh)[i] = o;
}

// persistent trickle convert: small blocks (128 thr, low regs) designed to
// co-reside with GEMM CTAs and consume spare DRAM bandwidth.
__global__ void __launch_bounds__(128)
convert_w_trickle(const float* __restrict__ W, __half* __restrict__ Wh,
                  size_t n8) {
    size_t stride = (size_t)gridDim.x * 128;
    for (size_t i = (size_t)blockIdx.x * 128 + threadIdx.x; i < n8; i += stride) {
        float4 a = ((const float4*)W)[i * 2];
        float4 b = ((const float4*)W)[i * 2 + 1];
        __half2 h0 = __floats2half2_rn(a.x, a.y);
        __half2 h1 = __floats2half2_rn(a.z, a.w);
        __half2 h2 = __floats2half2_rn(b.x, b.y);
        __half2 h3 = __floats2half2_rn(b.z, b.w);
        uint4 o;
        o.x = *(uint32_t*)&h0; o.y = *(uint32_t*)&h1;
        o.z = *(uint32_t*)&h2; o.w = *(uint32_t*)&h3;
        ((uint4*)Wh)[i] = o;
    }
}

// ---------------- grouped GEMM: fp16 mma (R6 champion, unchanged) -----------
template <bool DO_GELU, bool SCATTER>
__global__ void __launch_bounds__(256, 2)
moe_gemm(const __half* __restrict__ A, const __half* __restrict__ Wh,
         const float* __restrict__ bias, void* __restrict__ OutV,
         int K, int N, int ldo) {
    int e = g_tile_expert[blockIdx.y];
    if (e < 0) return;
    int row0 = g_tile_row[blockIdx.y];
    int n0 = blockIdx.x * BN;

    extern __shared__ __half smem[];
    int tid = threadIdx.x;
    int wid = tid >> 5, lane = tid & 31;

    const __half* Ap = A + (size_t)row0 * K;
    const __half* Bp = Wh + (size_t)e * K * N + n0;    // k-row stride = N

    uint32_t smem_u = (uint32_t)__cvta_generic_to_shared(smem);

    auto load_stage = [&](int j) {
        uint32_t base = smem_u + (uint32_t)(j % NSTAGE) * STAGE_BYTES;
        int kk = j * BK;
#pragma unroll
        for (int i = 0; i < 8; i++) {
            int c = tid + i * 256;
            if (c < 1024) {                      // A: K-major rows
                int r = c >> 3, c8 = c & 7;
                cpa16(base + (uint32_t)(r * APITCH + c8 * 8) * 2,
                      Ap + (size_t)r * K + kk + c8 * 8);
            } else {                             // B: N-major k-rows
                int cb = c - 1024;
                int r = cb >> 4, c8 = cb & 15;
                cpa16(base + TILE_A_BYTES + (uint32_t)(r * BPITCH + c8 * 8) * 2,
                      Bp + (size_t)(kk + r) * N + c8 * 8);
            }
        }
    };

    float acc[4][4][4];
#pragma unroll
    for (int mf = 0; mf < 4; mf++)
#pragma unroll
        for (int nf = 0; nf < 4; nf++)
#pragma unroll
            for (int i = 0; i < 4; i++) acc[mf][nf][i] = 0.0f;

    int wm = (wid & 1) * 64;      // 2 warps in m
    int wn = (wid >> 1) * 32;     // 4 warps in n
    int mq = lane >> 2, kq = lane & 3;

    uint32_t a_off0 = (uint32_t)(wm + (lane & 15)) * APITCH + ((lane >> 4) << 3);
    uint32_t b_krow = (uint32_t)(lane & 15);
    uint32_t b_noff = (uint32_t)(wn + ((lane >> 4) << 3));

    int NK = K / BK;
    load_stage(0); cp_commit();
    load_stage(1); cp_commit();

    for (int kt = 0; kt < NK; ++kt) {
        cp_wait<1>();
        __syncthreads();

        if (kt + 2 < NK) load_stage(kt + 2);
        cp_commit();

        uint32_t abase = smem_u + (uint32_t)(kt % NSTAGE) * STAGE_BYTES;
        uint32_t bbase = abase + TILE_A_BYTES;

#pragma unroll
        for (int k16 = 0; k16 < BK / 16; ++k16) {
            uint32_t koff = (uint32_t)(k16 * 16) * 2;
            uint32_t af[4][4];
#pragma unroll
            for (int mf = 0; mf < 4; mf++)
                ldm4(af[mf], abase + (a_off0 + (uint32_t)(mf * 16) * APITCH) * 2 + koff);
            uint32_t bregs[2][4];
#pragma unroll
            for (int nb = 0; nb < 2; nb++)
                ldm4t(bregs[nb], bbase
                      + ((uint32_t)(k16 * 16 + b_krow) * BPITCH
                         + b_noff + (uint32_t)(nb * 16)) * 2);
#pragma unroll
            for (int mf = 0; mf < 4; mf++)
#pragma unroll
                for (int nf = 0; nf < 4; nf++)
                    mma16(acc[mf][nf], af[mf], &bregs[nf >> 1][(nf & 1) * 2]);
        }
    }
    __syncthreads();

    // epilogue
    const float* be = bias + (size_t)e * N + n0;
#pragma unroll
    for (int mf = 0; mf < 4; mf++) {
        int m = wm + mf * 16 + mq;
        int r0, r1;
        bool s0 = true, s1 = true;
        if (SCATTER) {
            r0 = g_tok[row0 + m];     s0 = (r0 >= 0);
            r1 = g_tok[row0 + m + 8]; s1 = (r1 >= 0);
        } else {
            r0 = row0 + m; r1 = row0 + m + 8;
        }
#pragma unroll
        for (int nf = 0; nf < 4; nf++) {
            int nc = wn + nf * 8 + kq * 2;
            float b0 = be[nc], b1 = be[nc + 1];
            float v00 = acc[mf][nf][0] + b0, v01 = acc[mf][nf][1] + b1;
            float v10 = acc[mf][nf][2] + b0, v11 = acc[mf][nf][3] + b1;
            size_t col = (size_t)n0 + nc;
            if (DO_GELU) {
                __half* Out = (__half*)OutV;
                __half2 h0 = __floats2half2_rn(gelu_exact(v00), gelu_exact(v01));
                __half2 h1 = __floats2half2_rn(gelu_exact(v10), gelu_exact(v11));
                if (s0) *(__half2*)&Out[(size_t)r0 * ldo + col] = h0;
                if (s1) *(__half2*)&Out[(size_t)r1 * ldo + col] = h1;
            } else {
                float* Out = (float*)OutV;
                if (s0) *(float2*)&Out[(size_t)r0 * ldo + col] = make_float2(v00, v01);
                if (s1) *(float2*)&Out[(size_t)r1 * ldo + col] = make_float2(v10, v11);
            }
        }
    }
}

// ---------------- launch ----------------
extern "C" void kernel_launch(void* const* d_in, const int* in_sizes, int n_in,
                              void* d_out, int out_size) {
    const float* x  = (const float*)d_in[0];
    const float* Wr = (const float*)d_in[1];
    const float* br = (const float*)d_in[2];
    const float* W1 = (const float*)d_in[3];
    const float* b1 = (const float*)d_in[4];
    const float* W2 = (const float*)d_in[5];
    const float* b2 = (const float*)d_in[6];
    const float* W3 = (const float*)d_in[7];
    const float* b3 = (const float*)d_in[8];
    float* out = (float*)d_out;

    __half *xg, *h1, *h2, *wh1, *wh2, *wh3;
    cudaGetSymbolAddress((void**)&xg, g_xg);
    cudaGetSymbolAddress((void**)&h1, g_h1);
    cudaGetSymbolAddress((void**)&h2, g_h2);
    cudaGetSymbolAddress((void**)&wh1, g_wh1);
    cudaGetSymbolAddress((void**)&wh2, g_wh2);
    cudaGetSymbolAddress((void**)&wh3, g_wh3);

    cudaFuncSetAttribute((const void*)moe_gemm<true, false>,
                         cudaFuncAttributeMaxDynamicSharedMemorySize, SMEM_BYTES);
    cudaFuncSetAttribute((const void*)moe_gemm<false, true>,
                         cudaFuncAttributeMaxDynamicSharedMemorySize, SMEM_BYTES);

    // fork a side stream for weight conversion (created per call, not
    // destroyed: destroying forked streams during capture breaks the graph)
    cudaStream_t side;
    cudaStreamCreateWithFlags(&side, cudaStreamNonBlocking);
    cudaEvent_t evRoot, ev1, ev2, ev3;
    cudaEventCreateWithFlags(&evRoot, cudaEventDisableTiming);
    cudaEventCreateWithFlags(&ev1, cudaEventDisableTiming);
    cudaEventCreateWithFlags(&ev2, cudaEventDisableTiming);
    cudaEventCreateWithFlags(&ev3, cudaEventDisableTiming);

    cudaEventRecord(evRoot, 0);
    cudaStreamWaitEvent(side, evRoot, 0);

    size_t n1 = (size_t)NEXP * DIM * H1DIM / 8;
    size_t n2 = (size_t)NEXP * H1DIM * H2DIM / 8;
    size_t n3 = (size_t)NEXP * H2DIM * DIM / 8;

    // W1: full throughput, hidden under the routing chain
    convert_w<<<(unsigned)((n1 + 255) / 256), 256, 0, side>>>(W1, wh1, n1);
    cudaEventRecord(ev1, side);
    // W2/W3: persistent low-footprint trickle, co-resident with GEMM1/GEMM2
    convert_w_trickle<<<296, 128, 0, side>>>(W2, wh2, n2);
    cudaEventRecord(ev2, side);
    convert_w_trickle<<<296, 128, 0, side>>>(W3, wh3, n3);
    cudaEventRecord(ev3, side);

    // main stream: routing + gather
    init_kernel<<<1024, 256>>>();
    router_kernel<<<T_TOK / 8, 256>>>(x, Wr, br);
    schedule_kernel<<<1, 32>>>();
    scatter_gather_kernel<<<T_TOK, 128>>>(x);

    // expert MLP, each GEMM gated on the convert it consumes
    cudaStreamWaitEvent(0, ev1, 0);
    moe_gemm<true, false><<<dim3(H1DIM / BN, MAX_TILES), 256, SMEM_BYTES>>>(
        xg, wh1, b1, h1, DIM, H1DIM, H1DIM);
    cudaStreamWaitEvent(0, ev2, 0);
    moe_gemm<true, false><<<dim3(H2DIM / BN, MAX_TILES), 256, SMEM_BYTES>>>(
        h1, wh2, b2, h2, H1DIM, H2DIM, H2DIM);
    cudaStreamWaitEvent(0, ev3, 0);
    moe_gemm<false, true><<<dim3(DIM / BN, MAX_TILES), 256, SMEM_BYTES>>>(
        h2, wh3, b3, out, H2DIM, DIM, DIM);
}

// round 12
// speedup vs baseline: 1.2721x; 1.0882x over previous
#include <cuda_runtime.h>
#include <cuda_fp16.h>
#include <cstdint>
#include <math.h>

// ---------------- problem dims ----------------
#define T_TOK 8192
#define DIM   1024
#define NEXP  8
#define H1DIM 4096
#define H2DIM 2048
#define TPAD  9216
#define MAX_TILES 72

// ---------------- GEMM tile config (champion R6/R7) ----------------
#define BM 128
#define BN 128
#define BK 64
#define NSTAGE 3
#define APITCH 72                            // halfs/row A K-major
#define BPITCH 136                           // halfs/row B N-major
#define TILE_A_BYTES (BM * APITCH * 2)       // 18432
#define TILE_B_BYTES (BK * BPITCH * 2)       // 17408
#define STAGE_BYTES (TILE_A_BYTES + TILE_B_BYTES)   // 35840
#define SMEM_BYTES (NSTAGE * STAGE_BYTES)    // 107520 -> 2 CTAs/SM

// ---------------- device scratch ----------------
__device__ int g_expert_id[T_TOK];
__device__ int g_counts[NEXP];
__device__ int g_cursor[NEXP];
__device__ int g_offsets[NEXP];
__device__ int g_tok[TPAD];
__device__ int g_tile_expert[MAX_TILES];
__device__ int g_tile_row[MAX_TILES];
// NOTE: g_xg pad rows are never zeroed — they only feed pad rows of h1/h2,
// which the final scatter epilogue drops (g_tok<0). Values are always finite
// (zero-init at load; thereafter only our own fp16 writes), so no NaN hazard.
__device__ __half g_xg[(size_t)TPAD * DIM];
__device__ __half g_h1[(size_t)TPAD * H1DIM];
__device__ __half g_h2[(size_t)TPAD * H2DIM];
__device__ __half g_wh1[(size_t)NEXP * DIM * H1DIM];    // [e][k][n], layout = W1
__device__ __half g_wh2[(size_t)NEXP * H1DIM * H2DIM];
__device__ __half g_wh3[(size_t)NEXP * H2DIM * DIM];

// ---------------- helpers ----------------
__device__ __forceinline__ void mma16(float* c, const uint32_t* a, const uint32_t* b) {
    asm volatile(
        "mma.sync.aligned.m16n8k16.row.col.f32.f16.f16.f32 "
        "{%0,%1,%2,%3}, {%4,%5,%6,%7}, {%8,%9}, {%0,%1,%2,%3};\n"
        : "+f"(c[0]), "+f"(c[1]), "+f"(c[2]), "+f"(c[3])
        : "r"(a[0]), "r"(a[1]), "r"(a[2]), "r"(a[3]), "r"(b[0]), "r"(b[1]));
}

__device__ __forceinline__ void ldm4(uint32_t* r, uint32_t addr) {
    asm volatile("ldmatrix.sync.aligned.m8n8.x4.shared.b16 {%0,%1,%2,%3}, [%4];"
                 : "=r"(r[0]), "=r"(r[1]), "=r"(r[2]), "=r"(r[3]) : "r"(addr));
}
__device__ __forceinline__ void ldm4t(uint32_t* r, uint32_t addr) {
    asm volatile("ldmatrix.sync.aligned.m8n8.x4.trans.shared.b16 {%0,%1,%2,%3}, [%4];"
                 : "=r"(r[0]), "=r"(r[1]), "=r"(r[2]), "=r"(r[3]) : "r"(addr));
}

__device__ __forceinline__ void cpa16(uint32_t smem_addr, const void* gptr) {
    asm volatile("cp.async.cg.shared.global [%0], [%1], 16;\n"
                 :: "r"(smem_addr), "l"(gptr));
}
__device__ __forceinline__ void cp_commit() { asm volatile("cp.async.commit_group;\n"); }
template <int N>
__device__ __forceinline__ void cp_wait() { asm volatile("cp.async.wait_group %0;\n" :: "n"(N)); }

__device__ __forceinline__ float gelu_exact(float v) {
    return 0.5f * v * (1.0f + erff(v * 0.70710678118654752f));
}

// ---------------- routing phases ----------------
__global__ void init_kernel() {
    int i = blockIdx.x * 256 + threadIdx.x;
    if (i < TPAD) g_tok[i] = -1;
    if (i < NEXP) { g_counts[i] = 0; g_cursor[i] = 0; }
}

__global__ void router_kernel(const float* __restrict__ x,
                              const float* __restrict__ Wr,
                              const float* __restrict__ br) {
    __shared__ float s_wr[DIM * NEXP];
    __shared__ float s_br[NEXP];
    int tid = threadIdx.x;
    for (int i = tid; i < DIM * NEXP / 4; i += 256)
        ((float4*)s_wr)[i] = ((const float4*)Wr)[i];
    if (tid < NEXP) s_br[tid] = br[tid];
    __syncthreads();

    int warp = tid >> 5, lane = tid & 31;
    int t = blockIdx.x * 8 + warp;

    float acc[NEXP];
#pragma unroll
    for (int e = 0; e < NEXP; e++) acc[e] = 0.0f;
    const float* xr = x + (size_t)t * DIM;
    for (int d = lane; d < DIM; d += 32) {
        float xv = xr[d];
#pragma unroll
        for (int e = 0; e < NEXP; e++) acc[e] += xv * s_wr[d * NEXP + e];
    }
#pragma unroll
    for (int e = 0; e < NEXP; e++)
        for (int o = 16; o; o >>= 1) acc[e] += __shfl_down_sync(0xffffffffu, acc[e], o);

    if (lane == 0) {
        float best = acc[0] + s_br[0];
        int bi = 0;
        for (int e = 1; e < NEXP; e++) {
            float v = acc[e] + s_br[e];
            if (v > best) { best = v; bi = e; }   // first-max == jnp.argmax
        }
        g_expert_id[t] = bi;
        atomicAdd(&g_counts[bi], 1);
    }
}

__global__ void schedule_kernel() {
    if (threadIdx.x == 0 && blockIdx.x == 0) {
        int off = 0, t = 0;
        for (int e = 0; e < NEXP; e++) {
            g_offsets[e] = off;
            int c = g_counts[e];
            int tiles = (c + BM - 1) >> 7;
            for (int i = 0; i < tiles; i++) {
                g_tile_expert[t] = e;
                g_tile_row[t] = off + i * BM;
                t++;
            }
            off += tiles << 7;
        }
        for (; t < MAX_TILES; t++) { g_tile_expert[t] = -1; g_tile_row[t] = 0; }
    }
}

// fused scatter + gather + f16 convert: one block per token
__global__ void scatter_gather_kernel(const float* __restrict__ x) {
    __shared__ int s_pos;
    int t = blockIdx.x;
    if (threadIdx.x == 0) {
        int e = g_expert_id[t];
        int pos = g_offsets[e] + atomicAdd(&g_cursor[e], 1);
        g_tok[pos] = t;
        s_pos = pos;
    }
    __syncthreads();
    int pos = s_pos;
    const float4* xr = (const float4*)(x + (size_t)t * DIM);
    uint2* orow = (uint2*)(g_xg + (size_t)pos * DIM);
#pragma unroll
    for (int i = 0; i < 2; i++) {
        int c = threadIdx.x + i * 128;
        float4 v = xr[c];
        __half2 h0 = __floats2half2_rn(v.x, v.y);
        __half2 h1 = __floats2half2_rn(v.z, v.w);
        orow[c] = make_uint2(*(uint32_t*)&h0, *(uint32_t*)&h1);
    }
}

// streaming f32 -> f16 convert, layout preserved
__global__ void convert_w(const float* __restrict__ W, __half* __restrict__ Wh,
                          size_t n8) {
    size_t i = (size_t)blockIdx.x * 256 + threadIdx.x;
    if (i >= n8) return;
    float4 a = ((const float4*)W)[i * 2];
    float4 b = ((const float4*)W)[i * 2 + 1];
    __half2 h0 = __floats2half2_rn(a.x, a.y);
    __half2 h1 = __floats2half2_rn(a.z, a.w);
    __half2 h2 = __floats2half2_rn(b.x, b.y);
    __half2 h3 = __floats2half2_rn(b.z, b.w);
    uint4 o;
    o.x = *(uint32_t*)&h0; o.y = *(uint32_t*)&h1;
    o.z = *(uint32_t*)&h2; o.w = *(uint32_t*)&h3;
    ((uint4*)Wh)[i] = o;
}

// ---------------- grouped GEMM: fp16 mma (champion, unchanged) --------------
template <bool DO_GELU, bool SCATTER>
__global__ void __launch_bounds__(256, 2)
moe_gemm(const __half* __restrict__ A, const __half* __restrict__ Wh,
         const float* __restrict__ bias, void* __restrict__ OutV,
         int K, int N, int ldo) {
    int e = g_tile_expert[blockIdx.y];
    if (e < 0) return;
    int row0 = g_tile_row[blockIdx.y];
    int n0 = blockIdx.x * BN;

    extern __shared__ __half smem[];
    int tid = threadIdx.x;
    int wid = tid >> 5, lane = tid & 31;

    const __half* Ap = A + (size_t)row0 * K;
    const __half* Bp = Wh + (size_t)e * K * N + n0;    // k-row stride = N

    uint32_t smem_u = (uint32_t)__cvta_generic_to_shared(smem);

    auto load_stage = [&](int j) {
        uint32_t base = smem_u + (uint32_t)(j % NSTAGE) * STAGE_BYTES;
        int kk = j * BK;
#pragma unroll
        for (int i = 0; i < 8; i++) {
            int c = tid + i * 256;
            if (c < 1024) {                      // A: K-major rows
                int r = c >> 3, c8 = c & 7;
                cpa16(base + (uint32_t)(r * APITCH + c8 * 8) * 2,
                      Ap + (size_t)r * K + kk + c8 * 8);
            } else {                             // B: N-major k-rows
                int cb = c - 1024;
                int r = cb >> 4, c8 = cb & 15;
                cpa16(base + TILE_A_BYTES + (uint32_t)(r * BPITCH + c8 * 8) * 2,
                      Bp + (size_t)(kk + r) * N + c8 * 8);
            }
        }
    };

    float acc[4][4][4];
#pragma unroll
    for (int mf = 0; mf < 4; mf++)
#pragma unroll
        for (int nf = 0; nf < 4; nf++)
#pragma unroll
            for (int i = 0; i < 4; i++) acc[mf][nf][i] = 0.0f;

    int wm = (wid & 1) * 64;      // 2 warps in m
    int wn = (wid >> 1) * 32;     // 4 warps in n
    int mq = lane >> 2, kq = lane & 3;

    uint32_t a_off0 = (uint32_t)(wm + (lane & 15)) * APITCH + ((lane >> 4) << 3);
    uint32_t b_krow = (uint32_t)(lane & 15);
    uint32_t b_noff = (uint32_t)(wn + ((lane >> 4) << 3));

    int NK = K / BK;
    load_stage(0); cp_commit();
    load_stage(1); cp_commit();

    for (int kt = 0; kt < NK; ++kt) {
        cp_wait<1>();
        __syncthreads();

        if (kt + 2 < NK) load_stage(kt + 2);
        cp_commit();

        uint32_t abase = smem_u + (uint32_t)(kt % NSTAGE) * STAGE_BYTES;
        uint32_t bbase = abase + TILE_A_BYTES;

#pragma unroll
        for (int k16 = 0; k16 < BK / 16; ++k16) {
            uint32_t koff = (uint32_t)(k16 * 16) * 2;
            uint32_t af[4][4];
#pragma unroll
            for (int mf = 0; mf < 4; mf++)
                ldm4(af[mf], abase + (a_off0 + (uint32_t)(mf * 16) * APITCH) * 2 + koff);
            uint32_t bregs[2][4];
#pragma unroll
            for (int nb = 0; nb < 2; nb++)
                ldm4t(bregs[nb], bbase
                      + ((uint32_t)(k16 * 16 + b_krow) * BPITCH
                         + b_noff + (uint32_t)(nb * 16)) * 2);
#pragma unroll
            for (int mf = 0; mf < 4; mf++)
#pragma unroll
                for (int nf = 0; nf < 4; nf++)
                    mma16(acc[mf][nf], af[mf], &bregs[nf >> 1][(nf & 1) * 2]);
        }
    }
    __syncthreads();

    // epilogue
    const float* be = bias + (size_t)e * N + n0;
#pragma unroll
    for (int mf = 0; mf < 4; mf++) {
        int m = wm + mf * 16 + mq;
        int r0, r1;
        bool s0 = true, s1 = true;
        if (SCATTER) {
            r0 = g_tok[row0 + m];     s0 = (r0 >= 0);
            r1 = g_tok[row0 + m + 8]; s1 = (r1 >= 0);
        } else {
            r0 = row0 + m; r1 = row0 + m + 8;
        }
#pragma unroll
        for (int nf = 0; nf < 4; nf++) {
            int nc = wn + nf * 8 + kq * 2;
            float b0 = be[nc], b1 = be[nc + 1];
            float v00 = acc[mf][nf][0] + b0, v01 = acc[mf][nf][1] + b1;
            float v10 = acc[mf][nf][2] + b0, v11 = acc[mf][nf][3] + b1;
            size_t col = (size_t)n0 + nc;
            if (DO_GELU) {
                __half* Out = (__half*)OutV;
                __half2 h0 = __floats2half2_rn(gelu_exact(v00), gelu_exact(v01));
                __half2 h1 = __floats2half2_rn(gelu_exact(v10), gelu_exact(v11));
                if (s0) *(__half2*)&Out[(size_t)r0 * ldo + col] = h0;
                if (s1) *(__half2*)&Out[(size_t)r1 * ldo + col] = h1;
            } else {
                float* Out = (float*)OutV;
                if (s0) *(float2*)&Out[(size_t)r0 * ldo + col] = make_float2(v00, v01);
                if (s1) *(float2*)&Out[(size_t)r1 * ldo + col] = make_float2(v10, v11);
            }
        }
    }
}

// ---------------- launch ----------------
extern "C" void kernel_launch(void* const* d_in, const int* in_sizes, int n_in,
                              void* d_out, int out_size) {
    const float* x  = (const float*)d_in[0];
    const float* Wr = (const float*)d_in[1];
    const float* br = (const float*)d_in[2];
    const float* W1 = (const float*)d_in[3];
    const float* b1 = (const float*)d_in[4];
    const float* W2 = (const float*)d_in[5];
    const float* b2 = (const float*)d_in[6];
    const float* W3 = (const float*)d_in[7];
    const float* b3 = (const float*)d_in[8];
    float* out = (float*)d_out;

    __half *xg, *h1, *h2, *wh1, *wh2, *wh3;
    cudaGetSymbolAddress((void**)&xg, g_xg);
    cudaGetSymbolAddress((void**)&h1, g_h1);
    cudaGetSymbolAddress((void**)&h2, g_h2);
    cudaGetSymbolAddress((void**)&wh1, g_wh1);
    cudaGetSymbolAddress((void**)&wh2, g_wh2);
    cudaGetSymbolAddress((void**)&wh3, g_wh3);

    cudaFuncSetAttribute((const void*)moe_gemm<true, false>,
                         cudaFuncAttributeMaxDynamicSharedMemorySize, SMEM_BYTES);
    cudaFuncSetAttribute((const void*)moe_gemm<false, true>,
                         cudaFuncAttributeMaxDynamicSharedMemorySize, SMEM_BYTES);

    // fork: weight converts on a side stream (measured neutral vs serial, kept
    // because W1's convert hides under the routing chain). Stream/events are
    // created per call and not destroyed (graph-capture safety).
    cudaStream_t side;
    cudaStreamCreateWithFlags(&side, cudaStreamNonBlocking);
    cudaEvent_t evRoot, ev1, ev2, ev3;
    cudaEventCreateWithFlags(&evRoot, cudaEventDisableTiming);
    cudaEventCreateWithFlags(&ev1, cudaEventDisableTiming);
    cudaEventCreateWithFlags(&ev2, cudaEventDisableTiming);
    cudaEventCreateWithFlags(&ev3, cudaEventDisableTiming);

    cudaEventRecord(evRoot, 0);
    cudaStreamWaitEvent(side, evRoot, 0);

    size_t n1 = (size_t)NEXP * DIM * H1DIM / 8;
    size_t n2 = (size_t)NEXP * H1DIM * H2DIM / 8;
    size_t n3 = (size_t)NEXP * H2DIM * DIM / 8;
    convert_w<<<(unsigned)((n1 + 255) / 256), 256, 0, side>>>(W1, wh1, n1);
    cudaEventRecord(ev1, side);
    convert_w<<<(unsigned)((n2 + 255) / 256), 256, 0, side>>>(W2, wh2, n2);
    cudaEventRecord(ev2, side);
    convert_w<<<(unsigned)((n3 + 255) / 256), 256, 0, side>>>(W3, wh3, n3);
    cudaEventRecord(ev3, side);

    // main stream: routing + gather (no g_xg zeroing — pad rows are dead)
    init_kernel<<<(TPAD + 255) / 256, 256>>>();
    router_kernel<<<T_TOK / 8, 256>>>(x, Wr, br);
    schedule_kernel<<<1, 32>>>();
    scatter_gather_kernel<<<T_TOK, 128>>>(x);

    // expert MLP, each GEMM gated on the convert it consumes
    cudaStreamWaitEvent(0, ev1, 0);
    moe_gemm<true, false><<<dim3(H1DIM / BN, MAX_TILES), 256, SMEM_BYTES>>>(
        xg, wh1, b1, h1, DIM, H1DIM, H1DIM);
    cudaStreamWaitEvent(0, ev2, 0);
    moe_gemm<true, false><<<dim3(H2DIM / BN, MAX_TILES), 256, SMEM_BYTES>>>(
        h1, wh2, b2, h2, H1DIM, H2DIM, H2DIM);
    cudaStreamWaitEvent(0, ev3, 0);
    moe_gemm<false, true><<<dim3(DIM / BN, MAX_TILES), 256, SMEM_BYTES>>>(
        h2, wh3, b3, out, H2DIM, DIM, DIM);
}